// round 2
// baseline (speedup 1.0000x reference)
#include <cuda_runtime.h>
#include <cuda_bf16.h>
#include <cstdint>

// Fused: conv2d 3x3 SAME (NCHW, OIHW) -> min over C_out -> * 2.0
// x: (32, 64, 128, 128) f32, W: (128, 64, 3, 3) f32, out: (32, 1, 128, 128) f32
//
// Round 2: packed fp32 math via PTX fma.rn.f32x2 (SASS FFMA2, 2 MAC/lane/inst).
//  - pixel pairs: acc[8 oc][4 pairs] in 64-bit regs
//  - even x pairs loaded as aligned float2 from smem; odd pairs via mov.b64 pack
//  - weights staged in smem pre-duplicated as (w,w) so one LDS.64 = packed bcast

#define TILE_H 16
#define TILE_W 64
#define TPB    128
#define SX_COLS 68   // 66 used, padded stride (row stride 272B, 16B aligned)

__device__ __forceinline__ void fma2(unsigned long long& d,
                                     unsigned long long a,
                                     unsigned long long b) {
    asm("fma.rn.f32x2 %0, %1, %2, %0;" : "+l"(d) : "l"(a), "l"(b));
}

__device__ __forceinline__ unsigned long long pack2(float lo, float hi) {
    unsigned long long r;
    asm("mov.b64 %0, {%1, %2};" : "=l"(r) : "f"(lo), "f"(hi));
    return r;
}

__device__ __forceinline__ void unpack2(unsigned long long v, float& lo, float& hi) {
    asm("mov.b64 {%0, %1}, %2;" : "=f"(lo), "=f"(hi) : "l"(v));
}

__global__ void __launch_bounds__(TPB, 4)
conv_min_scale_kernel(const float* __restrict__ x,
                      const float* __restrict__ Wt,
                      float* __restrict__ out)
{
    const int b   = blockIdx.z;
    const int ty0 = blockIdx.y * TILE_H;
    const int tx0 = blockIdx.x * TILE_W;
    const int tid = threadIdx.x;
    const int ty  = tid >> 3;          // 0..15
    const int tx  = (tid & 7) << 3;    // 0,8,...,56 (even -> float2-aligned)

    __shared__ float  sX[TILE_H + 2][SX_COLS];   // 18 x 68 = 4.9 KB
    __shared__ float2 sW2[8][576];               // dup'd weights, 36.9 KB

    float minv[8];
#pragma unroll
    for (int p = 0; p < 8; ++p) minv[p] = 3.4028235e38f;

    const float* xb = x + (long long)b * 64 * 128 * 128;

    for (int occ = 0; occ < 16; ++occ) {
        __syncthreads();   // protect sW2 from previous chunk's readers
        // stage 8 oc of weights, duplicated into lanes of a float2
#pragma unroll 4
        for (int i = tid; i < 8 * 576; i += TPB) {
            int oc = i / 576;
            int r  = i - oc * 576;
            float w = Wt[(occ * 8 + oc) * 576 + r];
            sW2[oc][r] = make_float2(w, w);
        }

        unsigned long long acc[8][4];
#pragma unroll
        for (int o = 0; o < 8; ++o)
#pragma unroll
            for (int pp = 0; pp < 4; ++pp) acc[o][pp] = 0ULL;

        for (int ic = 0; ic < 64; ++ic) {
            __syncthreads();   // previous compute done reading sX
            const float* xc = xb + ic * 128 * 128;
            // stage 18 x 66 input tile (zero pad at borders)
            for (int i = tid; i < 18 * 66; i += TPB) {
                int r = i / 66;
                int c = i - r * 66;
                int gy = ty0 - 1 + r;
                int gx = tx0 - 1 + c;
                float v = 0.0f;
                if ((unsigned)gy < 128u && (unsigned)gx < 128u)
                    v = xc[gy * 128 + gx];
                sX[r][c] = v;
            }
            __syncthreads();

#pragma unroll
            for (int ky = 0; ky < 3; ++ky) {
                // even pairs e[k] = (x[2k], x[2k+1]), k=0..4, aligned LDS.64
                const float2* row2 =
                    reinterpret_cast<const float2*>(&sX[ty + ky][tx]);
                float2 ef[5];
#pragma unroll
                for (int k = 0; k < 5; ++k) ef[k] = row2[k];
                unsigned long long e[5], o[4];
#pragma unroll
                for (int k = 0; k < 5; ++k) e[k] = pack2(ef[k].x, ef[k].y);
#pragma unroll
                for (int k = 0; k < 4; ++k) o[k] = pack2(ef[k].y, ef[k + 1].x);

                const int wbase = ic * 9 + ky * 3;
#pragma unroll
                for (int oc = 0; oc < 8; ++oc) {
                    const unsigned long long* wrow =
                        reinterpret_cast<const unsigned long long*>(&sW2[oc][wbase]);
                    unsigned long long w0 = wrow[0];
                    unsigned long long w1 = wrow[1];
                    unsigned long long w2 = wrow[2];
#pragma unroll
                    for (int pp = 0; pp < 4; ++pp) {
                        fma2(acc[oc][pp], e[pp],     w0);  // taps (2pp,   2pp+1)
                        fma2(acc[oc][pp], o[pp],     w1);  //      (2pp+1, 2pp+2)
                        fma2(acc[oc][pp], e[pp + 1], w2);  //      (2pp+2, 2pp+3)
                    }
                }
            }
        }

        // reduce this oc-chunk into minv
#pragma unroll
        for (int o = 0; o < 8; ++o)
#pragma unroll
            for (int pp = 0; pp < 4; ++pp) {
                float lo, hi;
                unpack2(acc[o][pp], lo, hi);
                minv[2 * pp]     = fminf(minv[2 * pp],     lo);
                minv[2 * pp + 1] = fminf(minv[2 * pp + 1], hi);
            }
    }

    float* ob = out + (long long)b * 128 * 128;
    const int gy = ty0 + ty;
    const int gx = tx0 + tx;
#pragma unroll
    for (int p = 0; p < 8; ++p)
        ob[gy * 128 + gx + p] = minv[p] * 2.0f;
}

extern "C" void kernel_launch(void* const* d_in, const int* in_sizes, int n_in,
                              void* d_out, int out_size)
{
    const float* x  = (const float*)d_in[0];  // (32,64,128,128)
    const float* Wt = (const float*)d_in[1];  // (128,64,3,3)
    float* out = (float*)d_out;               // (32,1,128,128)

    dim3 grid(128 / TILE_W, 128 / TILE_H, 32); // (2, 8, 32)
    dim3 block(TPB);
    conv_min_scale_kernel<<<grid, block>>>(x, Wt, out);
}

// round 4
// speedup vs baseline: 2.5480x; 2.5480x over previous
#include <cuda_runtime.h>
#include <cstdint>
#include <cfloat>

// Fused conv2d 3x3 SAME -> min over C_out -> *2 via mma.sync tf32 implicit GEMM.
// x: (32,64,128,128) f32, W: (128,64,3,3) f32, out: (32,1,128,128) f32
//
// Per CTA: one batch image, one output row y.
//   D[px=128 (M)][oc=128 (N)] += A[px][K] * B[oc][K],  K=(ic,ky,kx)=576
// chunked 8 ic at a time (K_chunk=72 = 9 mma k-steps of 8).
// 8 warps as 2(m) x 4(n); warp tile 64x32 via m16n8k8 tf32 mma.sync.
// A/B staged in smem in *fragment order* with a lane-XOR swizzle so both the
// fill (STS) and the compute (LDS) are bank-conflict free.
// Epilogue: min over oc (regs -> shfl bfly over tg -> smem cross-warp) * 2.

#define TPB 256

static constexpr int A_OFF   = 0;
static constexpr int A_BYTES = 9 * 8 * 4 * 128;    // [s][mtile][reg][lane] = 36864
static constexpr int B_OFF   = A_OFF + A_BYTES;
static constexpr int B_BYTES = 9 * 16 * 2 * 128;   // [s][ntile][reg][lane] = 36864
static constexpr int RED_OFF = B_OFF + B_BYTES;
static constexpr int SMEM_TOTAL = RED_OFF + 128 * 4 * 4;  // + 2KB reduce buf

__device__ __forceinline__ uint32_t smem_u32(const void* p) {
    uint32_t a;
    asm("{ .reg .u64 t; cvta.to.shared.u64 t, %1; cvt.u32.u64 %0, t; }" : "=r"(a) : "l"(p));
    return a;
}
__device__ __forceinline__ void sts32(uint32_t a, uint32_t v) {
    asm volatile("st.shared.b32 [%0], %1;" :: "r"(a), "r"(v) : "memory");
}
__device__ __forceinline__ uint32_t lds32(uint32_t a) {
    uint32_t v;
    asm volatile("ld.shared.b32 %0, [%1];" : "=r"(v) : "r"(a));
    return v;
}
__device__ __forceinline__ uint32_t f32_to_tf32(float v) {
    uint32_t r;
    asm("cvt.rna.tf32.f32 %0, %1;" : "=r"(r) : "f"(v));
    return r;
}
__device__ __forceinline__ void mma_tf32(float& d0, float& d1, float& d2, float& d3,
                                         uint32_t a0, uint32_t a1, uint32_t a2, uint32_t a3,
                                         uint32_t b0, uint32_t b1) {
    asm volatile(
        "mma.sync.aligned.m16n8k8.row.col.f32.tf32.tf32.f32 "
        "{%0,%1,%2,%3}, {%4,%5,%6,%7}, {%8,%9}, {%0,%1,%2,%3};"
        : "+f"(d0), "+f"(d1), "+f"(d2), "+f"(d3)
        : "r"(a0), "r"(a1), "r"(a2), "r"(a3), "r"(b0), "r"(b1));
}

__global__ void __launch_bounds__(TPB, 2)
conv_min_mma_kernel(const float* __restrict__ x,
                    const float* __restrict__ Wt,
                    float* __restrict__ out)
{
    extern __shared__ char smem[];
    const uint32_t sb  = smem_u32(smem);
    const int tid    = threadIdx.x;
    const int lane   = tid & 31;
    const int wid    = tid >> 5;
    const int warp_m = wid >> 2;    // 0..1
    const int warp_n = wid & 3;     // 0..3
    const int y = blockIdx.x;
    const int b = blockIdx.y;

    const float* xb = x + (size_t)b * (64 * 128 * 128);

    uint32_t lx[4];
#pragma unroll
    for (int q = 0; q < 4; ++q) lx[q] = (uint32_t)((lane ^ q) << 2);

    float acc[4][4][4];
#pragma unroll
    for (int mt = 0; mt < 4; ++mt)
#pragma unroll
        for (int nt = 0; nt < 4; ++nt)
#pragma unroll
            for (int r = 0; r < 4; ++r) acc[mt][nt][r] = 0.0f;

    // A-fill per-thread constants: px fixed, k = ak0 + 2*i
    const int apx    = tid & 127;
    const int ak0    = tid >> 7;
    const int a_tile = apx >> 4;
    const int a_hi   = (apx >> 3) & 1;
    const int a_g    = apx & 7;
    const int a_swz  = ((a_tile & 1) << 1) | a_hi;

    // B-fill per-thread constants: one oc per thread-pair
    const int boc   = tid >> 1;
    const int bhalf = tid & 1;
    const int b_nt  = boc >> 3;
    const int b_g   = boc & 7;

    for (int c = 0; c < 8; ++c) {
        __syncthreads();   // previous chunk's compute done reading smem

        // ---- fill A (im2col, coalesced gmem; conflict-free STS) ----
#pragma unroll
        for (int i = 0; i < 36; ++i) {
            int k   = ak0 + 2 * i;           // 0..71
            int icl = k / 9;
            int rr  = k - icl * 9;
            int ky  = rr / 3;
            int kx  = rr - ky * 3;
            int gy  = y + ky - 1;
            int gx  = apx + kx - 1;
            float v = 0.0f;
            if ((unsigned)gy < 128u && (unsigned)gx < 128u)
                v = xb[(c * 8 + icl) * 16384 + gy * 128 + gx];
            int s     = k >> 3;
            int tg    = k & 3;
            int khalf = (k >> 2) & 1;
            int reg   = a_hi + 2 * khalf;
            int plane = (s * 8 + a_tile) * 4 + reg;
            uint32_t addr = sb + A_OFF + (uint32_t)(plane << 7) +
                            (uint32_t)((((a_g << 2) + tg) ^ a_swz) << 2);
            sts32(addr, f32_to_tf32(v));
        }

        // ---- fill B (W slice, float4 gmem; ~conflict-free STS) ----
        {
            const float4* W4 = reinterpret_cast<const float4*>(
                Wt + boc * 576 + c * 72 + bhalf * 36);
#pragma unroll
            for (int q = 0; q < 9; ++q) {
                float4 w = W4[q];
                float wv[4] = {w.x, w.y, w.z, w.w};
#pragma unroll
                for (int e = 0; e < 4; ++e) {
                    int k     = bhalf * 36 + q * 4 + e;
                    int s     = k >> 3;
                    int tg    = k & 3;
                    int reg   = (k >> 2) & 1;
                    int plane = (s * 16 + b_nt) * 2 + reg;
                    uint32_t addr = sb + B_OFF + (uint32_t)(plane << 7) +
                                    (uint32_t)((((b_g << 2) + tg) ^ (b_nt & 3)) << 2);
                    sts32(addr, f32_to_tf32(wv[e]));
                }
            }
        }
        __syncthreads();

        // ---- compute: 9 k-steps x (4 m-tiles x 4 n-tiles) mma ----
#pragma unroll
        for (int s = 0; s < 9; ++s) {
            const uint32_t a_s = sb + A_OFF + (uint32_t)(s << 12);
            const uint32_t b_s = sb + B_OFF + (uint32_t)(s << 12);
            uint32_t af[4][4];
#pragma unroll
            for (int mt = 0; mt < 4; ++mt) {
                int mtg = warp_m * 4 + mt;
#pragma unroll
                for (int r = 0; r < 4; ++r) {
                    int swz = ((mt & 1) << 1) | (r & 1);
                    af[mt][r] = lds32(a_s + (uint32_t)((mtg * 4 + r) << 7) + lx[swz]);
                }
            }
            uint32_t bf[4][2];
#pragma unroll
            for (int nt = 0; nt < 4; ++nt) {
                int ngl = warp_n * 4 + nt;
#pragma unroll
                for (int r = 0; r < 2; ++r)
                    bf[nt][r] = lds32(b_s + (uint32_t)((ngl * 2 + r) << 7) + lx[nt]);
            }
#pragma unroll
            for (int mt = 0; mt < 4; ++mt)
#pragma unroll
                for (int nt = 0; nt < 4; ++nt)
                    mma_tf32(acc[mt][nt][0], acc[mt][nt][1], acc[mt][nt][2], acc[mt][nt][3],
                             af[mt][0], af[mt][1], af[mt][2], af[mt][3],
                             bf[nt][0], bf[nt][1]);
        }
    }

    // ---- epilogue: min over oc, *2, write out ----
    float rmin[4][2];
#pragma unroll
    for (int mt = 0; mt < 4; ++mt) {
        float lo = fminf(acc[mt][0][0], acc[mt][0][1]);
        float hi = fminf(acc[mt][0][2], acc[mt][0][3]);
#pragma unroll
        for (int nt = 1; nt < 4; ++nt) {
            lo = fminf(lo, fminf(acc[mt][nt][0], acc[mt][nt][1]));
            hi = fminf(hi, fminf(acc[mt][nt][2], acc[mt][nt][3]));
        }
        rmin[mt][0] = lo;
        rmin[mt][1] = hi;
    }
    // min across tg (lane bits 0,1)
#pragma unroll
    for (int d = 1; d <= 2; d <<= 1)
#pragma unroll
        for (int mt = 0; mt < 4; ++mt)
#pragma unroll
            for (int h = 0; h < 2; ++h)
                rmin[mt][h] = fminf(rmin[mt][h],
                                    __shfl_xor_sync(0xffffffffu, rmin[mt][h], d));

    float* red = reinterpret_cast<float*>(smem + RED_OFF);
    if ((lane & 3) == 0) {
        int g = lane >> 2;
#pragma unroll
        for (int mt = 0; mt < 4; ++mt)
#pragma unroll
            for (int h = 0; h < 2; ++h) {
                int row = (warp_m * 4 + mt) * 16 + h * 8 + g;
                red[row * 4 + warp_n] = rmin[mt][h];
            }
    }
    __syncthreads();

    if (tid < 128) {
        float m = fminf(fminf(red[tid * 4 + 0], red[tid * 4 + 1]),
                        fminf(red[tid * 4 + 2], red[tid * 4 + 3]));
        out[(size_t)b * 16384 + y * 128 + tid] = m * 2.0f;
    }
}

extern "C" void kernel_launch(void* const* d_in, const int* in_sizes, int n_in,
                              void* d_out, int out_size)
{
    const float* x  = (const float*)d_in[0];
    const float* Wt = (const float*)d_in[1];
    float* out = (float*)d_out;

    cudaFuncSetAttribute(conv_min_mma_kernel,
                         cudaFuncAttributeMaxDynamicSharedMemorySize, SMEM_TOTAL);

    dim3 grid(128, 32);   // rows x batch
    conv_min_mma_kernel<<<grid, TPB, SMEM_TOTAL>>>(x, Wt, out);
}

// round 5
// speedup vs baseline: 7.0270x; 2.7578x over previous
#include <cuda_runtime.h>
#include <cstdint>
#include <cfloat>

// Fused conv2d 3x3 SAME -> min over C_out -> *2 via pipelined mma.sync tf32.
// x: (32,64,128,128) f32, W: (128,64,3,3) f32, out: (32,1,128,128) f32
//
// Per CTA (one image row y): D[px=128][oc=128] += A[px][K]*B[oc][K], K=576.
// Chunk = (8 ic, 1 ky) = 24 K = 3 k8-steps; 24 chunks, acc carried across all.
// B: pre-transformed W (fragment order, tf32-RNA) -> 8B cp.async, 3-stage.
// A: LDG(c+1) before compute(c), cvt+STS.128 after -> 2-stage, conflict-free.
// One __syncthreads per chunk. Epilogue: min over oc, *2.

#define TPB 256

static constexpr int A_SLAB = 12288;                  // 3 s x 8 mtg x 32 lane x 16B
static constexpr int B_SLAB = 12288;                  // 3 s x 16 ntg x 32 lane x 8B
static constexpr int RED_BYTES = 2048;
static constexpr int SMEM_TOTAL = 2 * A_SLAB + 3 * B_SLAB + RED_BYTES;  // 63488

__device__ float W2g[24 * 3072];   // W in fragment order per chunk, tf32-rounded

__device__ __forceinline__ uint32_t smem_u32(const void* p) {
    uint32_t a;
    asm("{ .reg .u64 t; cvta.to.shared.u64 t, %1; cvt.u32.u64 %0, t; }" : "=r"(a) : "l"(p));
    return a;
}
__device__ __forceinline__ uint32_t f32_to_tf32(float v) {
    uint32_t r;
    asm("cvt.rna.tf32.f32 %0, %1;" : "=r"(r) : "f"(v));
    return r;
}
__device__ __forceinline__ void mma_tf32(float& d0, float& d1, float& d2, float& d3,
                                         uint32_t a0, uint32_t a1, uint32_t a2, uint32_t a3,
                                         uint32_t b0, uint32_t b1) {
    asm volatile(
        "mma.sync.aligned.m16n8k8.row.col.f32.tf32.tf32.f32 "
        "{%0,%1,%2,%3}, {%4,%5,%6,%7}, {%8,%9}, {%0,%1,%2,%3};"
        : "+f"(d0), "+f"(d1), "+f"(d2), "+f"(d3)
        : "r"(a0), "r"(a1), "r"(a2), "r"(a3), "r"(b0), "r"(b1));
}

// ---- pre-kernel: W (OIHW) -> fragment-ordered, tf32-rounded W2g ----
// W2g[c*3072 + j*2 + r]: j=(s*16+ntg)*32+L; oc=ntg*8+L/4; k=s*8+(L&3)+4r;
// chunk c: ic0=(c/3)*8, ky=c%3; k=(icl,kx) with k=icl*3+kx.
__global__ void wxform_kernel(const float* __restrict__ Wt) {
    int f = blockIdx.x * TPB + threadIdx.x;
    if (f >= 24 * 3072) return;
    int c   = f / 3072;
    int rem = f - c * 3072;
    int j = rem >> 1, r = rem & 1;
    int L = j & 31, plane = j >> 5;
    int ntg = plane & 15, s = plane >> 4;
    int oc  = ntg * 8 + (L >> 2);
    int k   = s * 8 + (L & 3) + 4 * r;
    int icl = k / 3, kx = k - 3 * icl;
    int c3  = c / 3;
    int ic0 = c3 * 8, ky = c - 3 * c3;
    float v = Wt[oc * 576 + (ic0 + icl) * 9 + ky * 3 + kx];
    W2g[f] = __uint_as_float(f32_to_tf32(v));
}

__global__ void __launch_bounds__(TPB, 2)
conv_min_mma2_kernel(const float* __restrict__ x,
                     float* __restrict__ out)
{
    extern __shared__ char smem[];
    const uint32_t sbA = smem_u32(smem);
    const uint32_t sbB = sbA + 2 * A_SLAB;
    const int tid    = threadIdx.x;
    const int lane   = tid & 31;
    const int wid    = tid >> 5;
    const int warp_m = wid >> 2;
    const int warp_n = wid & 3;
    const int y = blockIdx.x;
    const int b = blockIdx.y;
    const float* xb = x + (size_t)b * (64 * 128 * 128);

    // ---- per-thread A-fill constants (3 slots of 16B each) ----
    int a_off0[3], a_off1[3];       // gmem offsets (icl*16384 + px + kx - 1), lo-px
    bool pll[3], plh[3], phl[3], phh[3];
    uint32_t a_sts[3];
#pragma unroll
    for (int i = 0; i < 3; ++i) {
        int j = tid + TPB * i;
        int L = j & 31, plane = j >> 5;
        int mtg = plane & 7, s = plane >> 3;
        int px = mtg * 16 + (L >> 2);
        int kl = s * 8 + (L & 3);
        int kh = kl + 4;
        int il = kl / 3, xl = kl - 3 * il;
        int ih = kh / 3, xh = kh - 3 * ih;
        a_off0[i] = il * 16384 + px + xl - 1;
        a_off1[i] = ih * 16384 + px + xh - 1;
        pll[i] = !(px == 0 && xl == 0);
        plh[i] = !(px == 0 && xh == 0);
        phl[i] = !(px + 8 == 127 && xl == 2);
        phh[i] = !(px + 8 == 127 && xh == 2);
        a_sts[i] = (uint32_t)(((s * 8 + mtg) * 32 + L) * 16);
    }

    float acc[4][4][4];
#pragma unroll
    for (int mt = 0; mt < 4; ++mt)
#pragma unroll
        for (int nt = 0; nt < 4; ++nt)
#pragma unroll
            for (int r = 0; r < 4; ++r) acc[mt][nt][r] = 0.0f;

    // ---- prologue: issue B(0), B(1); fill A(0) into buf 0 ----
#pragma unroll
    for (int cc = 0; cc < 2; ++cc) {
        uint32_t dst = sbB + cc * B_SLAB;
        const float* src = W2g + cc * 3072;
#pragma unroll
        for (int i = 0; i < 6; ++i) {
            int j = tid + TPB * i;
            uint64_t g = __cvta_generic_to_global((const void*)(src + j * 2));
            asm volatile("cp.async.ca.shared.global [%0], [%1], 8;"
                         :: "r"(dst + (uint32_t)(j * 8)), "l"(g) : "memory");
        }
        asm volatile("cp.async.commit_group;" ::: "memory");
    }
    {   // A(0): chunk 0 -> ic0=0, ky=0, gy=y-1
        int gy = y - 1;
        bool rowok = (unsigned)gy < 128u;
        const float* xrow = xb + gy * 128;
#pragma unroll
        for (int i = 0; i < 3; ++i) {
            float v0 = 0.f, v1 = 0.f, v2 = 0.f, v3 = 0.f;
            if (rowok && pll[i]) v0 = xrow[a_off0[i]];
            if (rowok && phl[i]) v1 = xrow[a_off0[i] + 8];
            if (rowok && plh[i]) v2 = xrow[a_off1[i]];
            if (rowok && phh[i]) v3 = xrow[a_off1[i] + 8];
            asm volatile("st.shared.v4.b32 [%0], {%1,%2,%3,%4};"
                         :: "r"(sbA + a_sts[i]),
                            "r"(f32_to_tf32(v0)), "r"(f32_to_tf32(v1)),
                            "r"(f32_to_tf32(v2)), "r"(f32_to_tf32(v3)) : "memory");
        }
    }

    int bR = 0;   // B read buffer = c % 3
#pragma unroll 1
    for (int c = 0; c < 24; ++c) {
        // wait own B(c) (one group may stay outstanding), then close compute(c-1)
        asm volatile("cp.async.wait_group 1;" ::: "memory");
        __syncthreads();

        // issue B(c+2) into buffer (c+2)%3 == (bR+2)%3
        if (c + 2 < 24) {
            int bW = bR - 1; if (bW < 0) bW += 3;
            uint32_t dst = sbB + (uint32_t)bW * B_SLAB;
            const float* src = W2g + (c + 2) * 3072;
#pragma unroll
            for (int i = 0; i < 6; ++i) {
                int j = tid + TPB * i;
                uint64_t g = __cvta_generic_to_global((const void*)(src + j * 2));
                asm volatile("cp.async.ca.shared.global [%0], [%1], 8;"
                             :: "r"(dst + (uint32_t)(j * 8)), "l"(g) : "memory");
            }
        }
        asm volatile("cp.async.commit_group;" ::: "memory");

        // prefetch A(c+1) into regs (LDG hidden under compute below)
        float av0[3], av1[3], av2[3], av3[3];
        if (c + 1 < 24) {
            int cn = c + 1;
            int c3 = cn / 3;
            int ic0 = c3 * 8, ky = cn - 3 * c3;
            int gy = y + ky - 1;
            bool rowok = (unsigned)gy < 128u;
            const float* xrow = xb + ic0 * 16384 + gy * 128;
#pragma unroll
            for (int i = 0; i < 3; ++i) {
                float v0 = 0.f, v1 = 0.f, v2 = 0.f, v3 = 0.f;
                if (rowok && pll[i]) v0 = xrow[a_off0[i]];
                if (rowok && phl[i]) v1 = xrow[a_off0[i] + 8];
                if (rowok && plh[i]) v2 = xrow[a_off1[i]];
                if (rowok && phh[i]) v3 = xrow[a_off1[i] + 8];
                av0[i] = v0; av1[i] = v1; av2[i] = v2; av3[i] = v3;
            }
        }

        // ---- compute chunk c ----
        const uint32_t aRd = sbA + (uint32_t)(c & 1) * A_SLAB;
        const uint32_t bRd = sbB + (uint32_t)bR * B_SLAB;
#pragma unroll
        for (int s = 0; s < 3; ++s) {
            uint32_t a0[4], a1[4], a2[4], a3[4];
#pragma unroll
            for (int mt = 0; mt < 4; ++mt) {
                uint32_t addr = aRd +
                    (uint32_t)(((s * 8 + warp_m * 4 + mt) * 32 + lane) * 16);
                asm volatile("ld.shared.v4.b32 {%0,%1,%2,%3}, [%4];"
                             : "=r"(a0[mt]), "=r"(a1[mt]), "=r"(a2[mt]), "=r"(a3[mt])
                             : "r"(addr));
            }
            uint32_t b0[4], b1[4];
#pragma unroll
            for (int nt = 0; nt < 4; ++nt) {
                uint32_t addr = bRd +
                    (uint32_t)(((s * 16 + warp_n * 4 + nt) * 32 + lane) * 8);
                asm volatile("ld.shared.v2.b32 {%0,%1}, [%2];"
                             : "=r"(b0[nt]), "=r"(b1[nt]) : "r"(addr));
            }
#pragma unroll
            for (int mt = 0; mt < 4; ++mt)
#pragma unroll
                for (int nt = 0; nt < 4; ++nt)
                    mma_tf32(acc[mt][nt][0], acc[mt][nt][1],
                             acc[mt][nt][2], acc[mt][nt][3],
                             a0[mt], a1[mt], a2[mt], a3[mt], b0[nt], b1[nt]);
        }

        // store prefetched A(c+1) into the other A buffer
        if (c + 1 < 24) {
            const uint32_t aWr = sbA + (uint32_t)((c + 1) & 1) * A_SLAB;
#pragma unroll
            for (int i = 0; i < 3; ++i) {
                asm volatile("st.shared.v4.b32 [%0], {%1,%2,%3,%4};"
                             :: "r"(aWr + a_sts[i]),
                                "r"(f32_to_tf32(av0[i])), "r"(f32_to_tf32(av1[i])),
                                "r"(f32_to_tf32(av2[i])), "r"(f32_to_tf32(av3[i]))
                             : "memory");
            }
        }
        bR = (bR == 2) ? 0 : bR + 1;
    }

    // ---- epilogue: min over oc, *2, write ----
    float rmin[4][2];
#pragma unroll
    for (int mt = 0; mt < 4; ++mt) {
        float lo = fminf(acc[mt][0][0], acc[mt][0][1]);
        float hi = fminf(acc[mt][0][2], acc[mt][0][3]);
#pragma unroll
        for (int nt = 1; nt < 4; ++nt) {
            lo = fminf(lo, fminf(acc[mt][nt][0], acc[mt][nt][1]));
            hi = fminf(hi, fminf(acc[mt][nt][2], acc[mt][nt][3]));
        }
        rmin[mt][0] = lo;
        rmin[mt][1] = hi;
    }
#pragma unroll
    for (int d = 1; d <= 2; d <<= 1)
#pragma unroll
        for (int mt = 0; mt < 4; ++mt)
#pragma unroll
            for (int h = 0; h < 2; ++h)
                rmin[mt][h] = fminf(rmin[mt][h],
                                    __shfl_xor_sync(0xffffffffu, rmin[mt][h], d));

    float* red = reinterpret_cast<float*>(smem + 2 * A_SLAB + 3 * B_SLAB);
    __syncthreads();
    if ((lane & 3) == 0) {
        int g = lane >> 2;
#pragma unroll
        for (int mt = 0; mt < 4; ++mt)
#pragma unroll
            for (int h = 0; h < 2; ++h) {
                int row = (warp_m * 4 + mt) * 16 + h * 8 + g;
                red[row * 4 + warp_n] = rmin[mt][h];
            }
    }
    __syncthreads();
    if (tid < 128) {
        float m = fminf(fminf(red[tid * 4 + 0], red[tid * 4 + 1]),
                        fminf(red[tid * 4 + 2], red[tid * 4 + 3]));
        out[(size_t)b * 16384 + y * 128 + tid] = m * 2.0f;
    }
}

extern "C" void kernel_launch(void* const* d_in, const int* in_sizes, int n_in,
                              void* d_out, int out_size)
{
    const float* x  = (const float*)d_in[0];
    const float* Wt = (const float*)d_in[1];
    float* out = (float*)d_out;

    cudaFuncSetAttribute(conv_min_mma2_kernel,
                         cudaFuncAttributeMaxDynamicSharedMemorySize, SMEM_TOTAL);

    wxform_kernel<<<(24 * 3072 + TPB - 1) / TPB, TPB>>>(Wt);

    dim3 grid(128, 32);   // rows x batch
    conv_min_mma2_kernel<<<grid, TPB, SMEM_TOTAL>>>(x, out);
}